// round 8
// baseline (speedup 1.0000x reference)
#include <cuda_runtime.h>
#include <cuda_bf16.h>
#include <cstdint>

// Problem dims
#define BB 2048   // batch
#define SS 128    // seq len
#define DD 512    // embedding dim
#define HH 2048   // hidden
#define CC 151    // classes

#define K1P (3*DD)   // 1536 : split-K for GEMM1 (sections A=[hi,lo,hi], B=[hi,hi,lo])
#define K2P (3*HH)   // 6144 : split-K for GEMM2
#define NPAD2 256    // padded class rows for B2
#define SPLITK2 8    // K-split for GEMM2 (6144/8 = 768 per chunk)

// Scratch (device globals — allocation is forbidden)
__device__ __nv_bfloat16 g_A1[(size_t)BB * K1P];             //  6 MB
__device__ __nv_bfloat16 g_B1[(size_t)HH * K1P];             //  6 MB
__device__ __nv_bfloat16 g_A2[(size_t)BB * K2P];             // 25 MB
__device__ __nv_bfloat16 g_B2[(size_t)NPAD2 * K2P];          //  3 MB
__device__ float         g_part[(size_t)SPLITK2 * BB * NPAD2]; // 16 MB

// ---------------------------------------------------------------------------
// helpers
// ---------------------------------------------------------------------------
__device__ __forceinline__ uint32_t smem_to_u32(const void* p) {
    uint32_t a;
    asm("{ .reg .u64 t; cvta.to.shared.u64 t, %1; cvt.u32.u64 %0, t; }" : "=r"(a) : "l"(p));
    return a;
}
__device__ __forceinline__ void cp_async16(uint32_t dst, const void* src) {
    asm volatile("cp.async.cg.shared.global [%0], [%1], 16;" :: "r"(dst), "l"(src) : "memory");
}
#define CP_ASYNC_COMMIT() asm volatile("cp.async.commit_group;" ::: "memory")
#define CP_ASYNC_WAIT0()  asm volatile("cp.async.wait_group 0;" ::: "memory")
#define CP_ASYNC_WAIT1()  asm volatile("cp.async.wait_group 1;" ::: "memory")

__device__ __forceinline__ void ldm_x4(uint32_t& r0, uint32_t& r1, uint32_t& r2, uint32_t& r3,
                                       uint32_t addr) {
    asm volatile("ldmatrix.sync.aligned.m8n8.x4.shared.b16 {%0,%1,%2,%3}, [%4];"
                 : "=r"(r0), "=r"(r1), "=r"(r2), "=r"(r3) : "r"(addr));
}
__device__ __forceinline__ void mma16816(float* c, const uint32_t* a, const uint32_t* b) {
    asm volatile(
        "mma.sync.aligned.m16n8k16.row.col.f32.bf16.bf16.f32 "
        "{%0,%1,%2,%3}, {%4,%5,%6,%7}, {%8,%9}, {%0,%1,%2,%3};"
        : "+f"(c[0]), "+f"(c[1]), "+f"(c[2]), "+f"(c[3])
        : "r"(a[0]), "r"(a[1]), "r"(a[2]), "r"(a[3]), "r"(b[0]), "r"(b[1]));
}
__device__ __forceinline__ uint32_t pack_bf2(__nv_bfloat16 lo, __nv_bfloat16 hi) {
    return ((uint32_t)__bfloat16_as_ushort(hi) << 16) | (uint32_t)__bfloat16_as_ushort(lo);
}
// smem tile: rows x 64B (BK=32 bf16). 16B chunk c in row r lives at
// r*64 + (c ^ ((r>>1)&3))*16  -> conflict-free for ldmatrix 8-row reads.
__device__ __forceinline__ uint32_t sw_off(int r, int c) {
    return (uint32_t)(r * 64 + ((c ^ ((r >> 1) & 3)) << 4));
}

// ---------------------------------------------------------------------------
// Kernel 1: embedding gather + masked mean -> split-bf16 A1 [BB][K1P]
// sections: [0,DD)=hi  [DD,2DD)=lo  [2DD,3DD)=hi
// ---------------------------------------------------------------------------
__global__ void embed_avg_kernel(const int* __restrict__ ids,
                                 const float4* __restrict__ emb) {
    int b = blockIdx.x;
    __shared__ int s_ids[SS];
    int tid = threadIdx.x;              // 0..127
    s_ids[tid] = ids[b * SS + tid];
    __syncthreads();

    float4 acc = make_float4(0.f, 0.f, 0.f, 0.f);
    int cnt = 0;
    #pragma unroll 4
    for (int s = 0; s < SS; ++s) {
        int id = s_ids[s];
        if (id != 0) {
            float4 v = emb[id * (DD / 4) + tid];
            acc.x += v.x; acc.y += v.y; acc.z += v.z; acc.w += v.w;
            cnt++;
        }
    }
    float inv = (cnt > 0) ? (1.0f / (float)cnt) : 0.0f;
    float v[4] = {acc.x * inv, acc.y * inv, acc.z * inv, acc.w * inv};

    __nv_bfloat16 h[4], l[4];
    #pragma unroll
    for (int j = 0; j < 4; j++) {
        h[j] = __float2bfloat16(v[j]);
        l[j] = __float2bfloat16(v[j] - __bfloat162float(h[j]));
    }
    uint2 hp = make_uint2(pack_bf2(h[0], h[1]), pack_bf2(h[2], h[3]));
    uint2 lp = make_uint2(pack_bf2(l[0], l[1]), pack_bf2(l[2], l[3]));
    size_t base = (size_t)b * K1P + tid * 4;
    *reinterpret_cast<uint2*>(&g_A1[base])          = hp;   // hi
    *reinterpret_cast<uint2*>(&g_A1[base + DD])     = lp;   // lo
    *reinterpret_cast<uint2*>(&g_A1[base + 2 * DD]) = hp;   // hi
}

// ---------------------------------------------------------------------------
// Transpose + split-convert: W [K][Nreal] f32 -> Bc [n][Kp] bf16 K-major.
// sections: [0,K)=hi  [K,2K)=hi  [2K,3K)=lo   (pairs with A's [hi,lo,hi])
// ---------------------------------------------------------------------------
__global__ void transconv_kernel(const float* __restrict__ W,
                                 __nv_bfloat16* __restrict__ Bc,
                                 int K, int Nreal, int Kp) {
    __shared__ float sm[32][33];
    int tx = threadIdx.x, ty = threadIdx.y;   // (32, 8)
    int n0 = blockIdx.x * 32, k0 = blockIdx.y * 32;

    #pragma unroll
    for (int r = 0; r < 4; r++) {
        int kk = k0 + ty + 8 * r;
        int nn = n0 + tx;
        sm[ty + 8 * r][tx] = (nn < Nreal) ? W[(size_t)kk * Nreal + nn] : 0.f;
    }
    __syncthreads();

    #pragma unroll
    for (int r = 0; r < 4; r++) {
        int nn = n0 + ty + 8 * r;
        int kk = k0 + tx;
        float v = sm[tx][ty + 8 * r];
        __nv_bfloat16 hi = __float2bfloat16(v);
        __nv_bfloat16 lo = __float2bfloat16(v - __bfloat162float(hi));
        size_t row = (size_t)nn * Kp;
        Bc[row + kk]         = hi;
        Bc[row + K + kk]     = hi;
        Bc[row + 2 * K + kk] = lo;
    }
}

// ---------------------------------------------------------------------------
// mma.sync bf16 GEMM, NT form: C[128 x 256] = A[128xKc] . B[256xKc]^T
// Both operands K-contiguous (row stride ld). BK=32, 3-stage cp.async
// pipeline, ONE __syncthreads per iteration.
// 8 warps in 2(M) x 4(N); warp tile 64x64 -> 64 independent MMAs per k16
// (deep tensor-pipe ILP; this kernel runs 1 CTA/SM by design).
// MODE 0: v = relu(d + bias[n]); write split-bf16 rows to outS (stride K2P).
// MODE 1: write raw f32 partial to outF[(z*BB+m)*NPAD2 + n].
// Dynamic smem: A stages 3 x 8 KB at [0, 24K); B stages 3 x 16 KB at [24K, 72K).
// ---------------------------------------------------------------------------
template <int MODE>
__global__ __launch_bounds__(256, 1)
void hmma_gemm_kernel(const __nv_bfloat16* __restrict__ A,
                      const __nv_bfloat16* __restrict__ Bm,
                      const float* __restrict__ bias,
                      __nv_bfloat16* __restrict__ outS,
                      float* __restrict__ outF,
                      int ld, int kChunk) {
    extern __shared__ __align__(16) unsigned char smem_dyn[];
    const uint32_t sA = smem_to_u32(smem_dyn);            // 3 x 8192
    const uint32_t sB = sA + 3 * 8192;                    // 3 x 16384

    const int tid  = threadIdx.x;
    const int wid  = tid >> 5;
    const int lane = tid & 31;
    const int m0 = blockIdx.y * 128;
    const int n0 = blockIdx.x * 256;
    const int koff = blockIdx.z * kChunk;

    const __nv_bfloat16* Ap = A + (size_t)m0 * ld + koff;
    const __nv_bfloat16* Bp = Bm + (size_t)n0 * ld + koff;

    const int niter = kChunk / 32;   // >= 2 always here

    // stage tile for iteration 'it' into stage buffer 'buf' (0..2)
    auto stage = [&](int it, int buf) {
        const __nv_bfloat16* a_src = Ap + it * 32;
        const __nv_bfloat16* b_src = Bp + it * 32;
        uint32_t dA = sA + buf * 8192;
        uint32_t dB = sB + buf * 16384;
        #pragma unroll
        for (int p = 0; p < 2; p++) {            // A: 512 16B chunks
            int i = p * 256 + tid;
            int r = i >> 2;                      // row 0..127
            int c = i & 3;
            cp_async16(dA + sw_off(r, c), a_src + (size_t)r * ld + c * 8);
        }
        #pragma unroll
        for (int p = 0; p < 4; p++) {            // B: 1024 16B chunks
            int i = p * 256 + tid;
            int r = i >> 2;                      // row 0..255
            int c = i & 3;
            cp_async16(dB + sw_off(r, c), b_src + (size_t)r * ld + c * 8);
        }
    };

    const int wm = (wid >> 2) * 64;   // 0 or 64        (M half)
    const int wn = (wid & 3) * 64;    // 0,64,128,192   (N quarter)

    float acc[4][8][4];
    #pragma unroll
    for (int i = 0; i < 4; i++)
        #pragma unroll
        for (int j = 0; j < 8; j++)
            #pragma unroll
            for (int q = 0; q < 4; q++) acc[i][j][q] = 0.f;

    // prologue: prefetch tiles 0 and 1
    stage(0, 0);
    CP_ASYNC_COMMIT();
    stage(1, 1);
    CP_ASYNC_COMMIT();

    for (int it = 0; it < niter; it++) {
        int buf = it % 3;
        CP_ASYNC_WAIT1();      // <=1 group pending -> stage(it) has landed
        __syncthreads();       // all warps past compute(it-1); buf (it-1)%3 free

        if (it + 2 < niter) {
            stage(it + 2, (it + 2) % 3);
            CP_ASYNC_COMMIT();
        }

        uint32_t aBase = sA + buf * 8192;
        uint32_t bBase = sB + buf * 16384;
        #pragma unroll
        for (int ks = 0; ks < 2; ks++) {
            uint32_t a[4][4];
            #pragma unroll
            for (int mi = 0; mi < 4; mi++) {
                int r = wm + mi * 16 + (lane & 15);
                int c = ks * 2 + (lane >> 4);
                ldm_x4(a[mi][0], a[mi][1], a[mi][2], a[mi][3], aBase + sw_off(r, c));
            }
            uint32_t b[8][2];
            #pragma unroll
            for (int nj = 0; nj < 4; nj++) {     // 4 loads -> 8 n8 frags
                int r = wn + nj * 16 + (lane & 15);
                int c = ks * 2 + (lane >> 4);
                uint32_t r0, r1, r2, r3;
                ldm_x4(r0, r1, r2, r3, bBase + sw_off(r, c));
                b[nj * 2 + 0][0] = r0;  b[nj * 2 + 1][0] = r1;
                b[nj * 2 + 0][1] = r2;  b[nj * 2 + 1][1] = r3;
            }
            #pragma unroll
            for (int mi = 0; mi < 4; mi++)
                #pragma unroll
                for (int nj = 0; nj < 8; nj++)
                    mma16816(acc[mi][nj], a[mi], b[nj]);
        }
    }

    // Epilogue. acc frag (mi,nj): rows wm+mi*16 + (lane>>2) and +8;
    // cols wn+nj*8 + 2*(lane&3) + {0,1}.
    const int rr = lane >> 2;
    const int cpair = (lane & 3) * 2;
    #pragma unroll
    for (int mi = 0; mi < 4; mi++) {
        #pragma unroll
        for (int nj = 0; nj < 8; nj++) {
            int nl = wn + nj * 8 + cpair;          // local col (even)
            int n = n0 + nl;
            float b0 = 0.f, b1 = 0.f;
            if (MODE == 0) {
                b0 = __ldg(&bias[n]);
                b1 = __ldg(&bias[n + 1]);
            }
            #pragma unroll
            for (int h = 0; h < 2; h++) {          // h=0: row rr, h=1: row rr+8
                int m = m0 + wm + mi * 16 + rr + h * 8;
                float v0 = acc[mi][nj][2 * h + 0];
                float v1 = acc[mi][nj][2 * h + 1];
                if (MODE == 0) {
                    v0 = fmaxf(v0 + b0, 0.f);
                    v1 = fmaxf(v1 + b1, 0.f);
                    __nv_bfloat16 h0 = __float2bfloat16(v0);
                    __nv_bfloat16 h1 = __float2bfloat16(v1);
                    __nv_bfloat16 l0 = __float2bfloat16(v0 - __bfloat162float(h0));
                    __nv_bfloat16 l1 = __float2bfloat16(v1 - __bfloat162float(h1));
                    uint32_t hp = pack_bf2(h0, h1);
                    uint32_t lp = pack_bf2(l0, l1);
                    size_t rowb = (size_t)m * K2P + n;
                    *reinterpret_cast<uint32_t*>(&outS[rowb])          = hp;
                    *reinterpret_cast<uint32_t*>(&outS[rowb + HH])     = lp;
                    *reinterpret_cast<uint32_t*>(&outS[rowb + 2 * HH]) = hp;
                } else {
                    size_t zb = (size_t)blockIdx.z * BB;
                    *reinterpret_cast<float2*>(&outF[(zb + m) * NPAD2 + n]) =
                        make_float2(v0, v1);
                }
            }
        }
    }
}

// ---------------------------------------------------------------------------
// Reduce split-K partials: out[m][n] = b2[n] + sum_s part[s][m][n], n < CC
// ---------------------------------------------------------------------------
__global__ void reduce_k2_kernel(const float* __restrict__ part,
                                 const float* __restrict__ b2,
                                 float* __restrict__ out) {
    int m = blockIdx.x;
    int n = threadIdx.x;            // 160 threads
    if (n < CC) {
        float s = b2[n];
        #pragma unroll
        for (int z = 0; z < SPLITK2; z++)
            s += part[((size_t)z * BB + m) * NPAD2 + n];
        out[(size_t)m * CC + n] = s;
    }
}

// ---------------------------------------------------------------------------
// Launch. Inputs: ids i32[2048,128], emb f32[50000,512], W1 f32[512,2048],
// b1 f32[2048], W2 f32[2048,151], b2 f32[151]. Output f32[2048,151].
// ---------------------------------------------------------------------------
extern "C" void kernel_launch(void* const* d_in, const int* in_sizes, int n_in,
                              void* d_out, int out_size) {
    const int*    ids = (const int*)d_in[0];
    const float4* emb = (const float4*)d_in[1];
    const float*  W1  = (const float*)d_in[2];
    const float*  b1  = (const float*)d_in[3];
    const float*  W2  = (const float*)d_in[4];
    const float*  b2  = (const float*)d_in[5];
    float*        out = (float*)d_out;

    __nv_bfloat16 *A1, *B1, *A2, *B2;
    float* part;
    cudaGetSymbolAddress((void**)&A1, g_A1);
    cudaGetSymbolAddress((void**)&B1, g_B1);
    cudaGetSymbolAddress((void**)&A2, g_A2);
    cudaGetSymbolAddress((void**)&B2, g_B2);
    cudaGetSymbolAddress((void**)&part, g_part);

    const int SMEM_GEMM = 3 * (8192 + 16384);   // 72 KB (3-stage A + B)
    static bool attr_done = false;
    if (!attr_done) {
        cudaFuncSetAttribute(hmma_gemm_kernel<0>,
                             cudaFuncAttributeMaxDynamicSharedMemorySize, SMEM_GEMM);
        cudaFuncSetAttribute(hmma_gemm_kernel<1>,
                             cudaFuncAttributeMaxDynamicSharedMemorySize, SMEM_GEMM);
        attr_done = true;
    }

    // 1) gather + masked mean -> split-bf16 A1
    embed_avg_kernel<<<BB, 128>>>(ids, emb);

    // 2) weight conversions (independent of (1))
    transconv_kernel<<<dim3(HH / 32, DD / 32), dim3(32, 8)>>>(W1, B1, DD, HH, K1P);
    transconv_kernel<<<dim3(NPAD2 / 32, HH / 32), dim3(32, 8)>>>(W2, B2, HH, CC, K2P);

    // 3) h = relu(A1 . B1^T + b1) -> split-bf16 A2   [2048 x 2048], 128 CTAs
    hmma_gemm_kernel<0><<<dim3(HH / 256, BB / 128, 1), 256, SMEM_GEMM>>>(
        A1, B1, b1, A2, nullptr, K1P, K1P);

    // 4) partials = A2 . B2^T over K chunks          [2048 x 256] x 8, 128 CTAs
    hmma_gemm_kernel<1><<<dim3(NPAD2 / 256, BB / 128, SPLITK2), 256, SMEM_GEMM>>>(
        A2, B2, nullptr, nullptr, part, K2P, K2P / SPLITK2);

    // 5) out = b2 + sum partials (n < 151)
    reduce_k2_kernel<<<BB, 160>>>(part, b2, out);
}

// round 10
// speedup vs baseline: 1.3121x; 1.3121x over previous
#include <cuda_runtime.h>
#include <cuda_fp16.h>
#include <cstdint>

// Problem dims
#define BB 2048   // batch
#define SS 128    // seq len
#define DD 512    // embedding dim
#define HH 2048   // hidden
#define CC 151    // classes

// fp16 2-section split: A=[hi,lo], B=[hi,hi]  (drops a*b_lo, ~2^-12.5 rel)
#define K1P (2*DD)   // 1024
#define K2P (2*HH)   // 4096
#define NPAD2 256    // padded class rows for B2
#define SPLITK2 8    // K-split for GEMM2 (4096/8 = 512 per chunk)

// Scratch (device globals — allocation is forbidden)
__device__ __half g_A1[(size_t)BB * K1P];               //  4 MB
__device__ __half g_B1[(size_t)HH * K1P];               //  4 MB
__device__ __half g_A2[(size_t)BB * K2P];               // 16 MB
__device__ __half g_B2[(size_t)NPAD2 * K2P];            //  2 MB
__device__ float  g_part[(size_t)SPLITK2 * BB * NPAD2]; // 16 MB

// ---------------------------------------------------------------------------
// helpers
// ---------------------------------------------------------------------------
__device__ __forceinline__ uint32_t smem_to_u32(const void* p) {
    uint32_t a;
    asm("{ .reg .u64 t; cvta.to.shared.u64 t, %1; cvt.u32.u64 %0, t; }" : "=r"(a) : "l"(p));
    return a;
}
__device__ __forceinline__ void cp_async16(uint32_t dst, const void* src) {
    asm volatile("cp.async.cg.shared.global [%0], [%1], 16;" :: "r"(dst), "l"(src) : "memory");
}
#define CP_ASYNC_COMMIT() asm volatile("cp.async.commit_group;" ::: "memory")
#define CP_ASYNC_WAIT0()  asm volatile("cp.async.wait_group 0;" ::: "memory")
#define CP_ASYNC_WAIT1()  asm volatile("cp.async.wait_group 1;" ::: "memory")

__device__ __forceinline__ void ldm_x4(uint32_t& r0, uint32_t& r1, uint32_t& r2, uint32_t& r3,
                                       uint32_t addr) {
    asm volatile("ldmatrix.sync.aligned.m8n8.x4.shared.b16 {%0,%1,%2,%3}, [%4];"
                 : "=r"(r0), "=r"(r1), "=r"(r2), "=r"(r3) : "r"(addr));
}
__device__ __forceinline__ void mma16816(float* c, const uint32_t* a, const uint32_t* b) {
    asm volatile(
        "mma.sync.aligned.m16n8k16.row.col.f32.f16.f16.f32 "
        "{%0,%1,%2,%3}, {%4,%5,%6,%7}, {%8,%9}, {%0,%1,%2,%3};"
        : "+f"(c[0]), "+f"(c[1]), "+f"(c[2]), "+f"(c[3])
        : "r"(a[0]), "r"(a[1]), "r"(a[2]), "r"(a[3]), "r"(b[0]), "r"(b[1]));
}
__device__ __forceinline__ uint32_t pack_h2(__half lo, __half hi) {
    return ((uint32_t)__half_as_ushort(hi) << 16) | (uint32_t)__half_as_ushort(lo);
}
// smem tile: rows x 64B (BK=32 fp16). 16B chunk c in row r lives at
// r*64 + (c ^ ((r>>1)&3))*16  -> conflict-free for ldmatrix 8-row reads.
__device__ __forceinline__ uint32_t sw_off(int r, int c) {
    return (uint32_t)(r * 64 + ((c ^ ((r >> 1) & 3)) << 4));
}

// ---------------------------------------------------------------------------
// Kernel 1: embedding gather + masked mean -> fp16-split A1 [BB][K1P]
// sections: [0,DD)=hi  [DD,2DD)=lo
// Branch-free: table row 0 is all-zero, so summing it unconditionally is
// exact; the mask count comes from __syncthreads_count.
// ---------------------------------------------------------------------------
__global__ void embed_avg_kernel(const int* __restrict__ ids,
                                 const float4* __restrict__ emb) {
    int b = blockIdx.x;
    __shared__ int s_ids[SS];
    int tid = threadIdx.x;              // 0..127
    int myid = ids[b * SS + tid];
    s_ids[tid] = myid;
    int cnt = __syncthreads_count(myid != 0);   // barrier + popcount over block

    float4 acc = make_float4(0.f, 0.f, 0.f, 0.f);
    #pragma unroll 8
    for (int s = 0; s < SS; ++s) {
        float4 v = emb[s_ids[s] * (DD / 4) + tid];   // id==0 row adds zeros
        acc.x += v.x; acc.y += v.y; acc.z += v.z; acc.w += v.w;
    }
    float inv = (cnt > 0) ? (1.0f / (float)cnt) : 0.0f;
    float v[4] = {acc.x * inv, acc.y * inv, acc.z * inv, acc.w * inv};

    __half h[4], l[4];
    #pragma unroll
    for (int j = 0; j < 4; j++) {
        h[j] = __float2half(v[j]);
        l[j] = __float2half(v[j] - __half2float(h[j]));
    }
    uint2 hp = make_uint2(pack_h2(h[0], h[1]), pack_h2(h[2], h[3]));
    uint2 lp = make_uint2(pack_h2(l[0], l[1]), pack_h2(l[2], l[3]));
    size_t base = (size_t)b * K1P + tid * 4;
    *reinterpret_cast<uint2*>(&g_A1[base])      = hp;   // hi
    *reinterpret_cast<uint2*>(&g_A1[base + DD]) = lp;   // lo
}

// ---------------------------------------------------------------------------
// Transpose + convert: W [K][Nreal] f32 -> Bc [n][Kp=2K] fp16 K-major.
// sections: [0,K)=hi  [K,2K)=hi  (B side carries hi twice; lo never needed)
// ---------------------------------------------------------------------------
__global__ void transconv_kernel(const float* __restrict__ W,
                                 __half* __restrict__ Bc,
                                 int K, int Nreal, int Kp) {
    __shared__ float sm[32][33];
    int tx = threadIdx.x, ty = threadIdx.y;   // (32, 8)
    int n0 = blockIdx.x * 32, k0 = blockIdx.y * 32;

    #pragma unroll
    for (int r = 0; r < 4; r++) {
        int kk = k0 + ty + 8 * r;
        int nn = n0 + tx;
        sm[ty + 8 * r][tx] = (nn < Nreal) ? W[(size_t)kk * Nreal + nn] : 0.f;
    }
    __syncthreads();

    #pragma unroll
    for (int r = 0; r < 4; r++) {
        int nn = n0 + ty + 8 * r;
        int kk = k0 + tx;
        __half hi = __float2half(sm[tx][ty + 8 * r]);
        size_t row = (size_t)nn * Kp;
        Bc[row + kk]     = hi;
        Bc[row + K + kk] = hi;
    }
}

// ---------------------------------------------------------------------------
// mma.sync fp16 GEMM, NT form: C[128x128] = A[128xKc] . B[128xKc]^T
// Both operands K-contiguous (row stride ld). BK=32, 3-stage cp.async
// pipeline, ONE __syncthreads per iteration (R6 config — best measured).
// 8 warps: warp (wid>>2) -> 64-row half, (wid&3) -> 32-col quarter.
// MODE 0: v = relu(d + bias[n]); write fp16 [hi,lo] rows to outS (stride K2P).
// MODE 1: write raw f32 partial to outF[(z*BB+m)*NPAD2 + n].
// Dynamic smem: A stages 3 x 8 KB at [0,24K); B stages 3 x 8 KB at [24K,48K).
// ---------------------------------------------------------------------------
template <int MODE>
__global__ __launch_bounds__(256, 2)
void hmma_gemm_kernel(const __half* __restrict__ A,
                      const __half* __restrict__ Bm,
                      const float* __restrict__ bias,
                      __half* __restrict__ outS,
                      float* __restrict__ outF,
                      int ld, int kChunk) {
    extern __shared__ __align__(16) unsigned char smem_dyn[];
    const uint32_t sA = smem_to_u32(smem_dyn);            // 3 x 8192
    const uint32_t sB = sA + 3 * 8192;                    // 3 x 8192

    const int tid  = threadIdx.x;
    const int wid  = tid >> 5;
    const int lane = tid & 31;
    const int m0 = blockIdx.y * 128;
    const int n0 = blockIdx.x * 128;
    const int koff = blockIdx.z * kChunk;

    const __half* Ap = A + (size_t)m0 * ld + koff;
    const __half* Bp = Bm + (size_t)n0 * ld + koff;

    const int niter = kChunk / 32;

    // stage tile for iteration 'it' into stage buffer 'buf' (0..2)
    auto stage = [&](int it, int buf) {
        const __half* a_src = Ap + it * 32;
        const __half* b_src = Bp + it * 32;
        uint32_t dA = sA + buf * 8192;
        uint32_t dB = sB + buf * 8192;
        #pragma unroll
        for (int p = 0; p < 2; p++) {
            int i = p * 256 + tid;     // 0..511 : 16B chunks
            int r = i >> 2;            // row 0..127
            int c = i & 3;             // 16B chunk in row
            uint32_t off = sw_off(r, c);
            cp_async16(dA + off, a_src + (size_t)r * ld + c * 8);
            cp_async16(dB + off, b_src + (size_t)r * ld + c * 8);
        }
    };

    const int wm = (wid >> 2) * 64;
    const int wn = (wid & 3) * 32;

    float acc[4][4][4];
    #pragma unroll
    for (int i = 0; i < 4; i++)
        #pragma unroll
        for (int j = 0; j < 4; j++)
            #pragma unroll
            for (int q = 0; q < 4; q++) acc[i][j][q] = 0.f;

    // prologue: prefetch tiles 0 and 1
    stage(0, 0);
    CP_ASYNC_COMMIT();
    stage(1, 1);
    CP_ASYNC_COMMIT();

    for (int it = 0; it < niter; it++) {
        int buf = it % 3;
        CP_ASYNC_WAIT1();      // <=1 group pending -> stage(it) has landed
        __syncthreads();       // all warps past compute(it-1); buf (it-1)%3 free

        if (it + 2 < niter) {
            stage(it + 2, (it + 2) % 3);
            CP_ASYNC_COMMIT();
        }

        uint32_t aBase = sA + buf * 8192;
        uint32_t bBase = sB + buf * 8192;
        #pragma unroll
        for (int ks = 0; ks < 2; ks++) {
            uint32_t a[4][4];
            #pragma unroll
            for (int mi = 0; mi < 4; mi++) {
                int r = wm + mi * 16 + (lane & 15);
                int c = ks * 2 + (lane >> 4);
                ldm_x4(a[mi][0], a[mi][1], a[mi][2], a[mi][3], aBase + sw_off(r, c));
            }
            uint32_t b[4][2];
            #pragma unroll
            for (int nj = 0; nj < 2; nj++) {
                int r = wn + nj * 16 + (lane & 15);
                int c = ks * 2 + (lane >> 4);
                uint32_t r0, r1, r2, r3;
                ldm_x4(r0, r1, r2, r3, bBase + sw_off(r, c));
                b[nj * 2 + 0][0] = r0;  b[nj * 2 + 1][0] = r1;
                b[nj * 2 + 0][1] = r2;  b[nj * 2 + 1][1] = r3;
            }
            #pragma unroll
            for (int mi = 0; mi < 4; mi++)
                #pragma unroll
                for (int nj = 0; nj < 4; nj++)
                    mma16816(acc[mi][nj], a[mi], b[nj]);
        }
    }

    // Epilogue. acc frag (mi,nj): rows wm+mi*16 + (lane>>2) and +8;
    // cols wn+nj*8 + 2*(lane&3) + {0,1}.
    const int rr = lane >> 2;
    const int cpair = (lane & 3) * 2;
    #pragma unroll
    for (int mi = 0; mi < 4; mi++) {
        #pragma unroll
        for (int nj = 0; nj < 4; nj++) {
            int nl = wn + nj * 8 + cpair;          // local col (even)
            int n = n0 + nl;
            float b0 = 0.f, b1 = 0.f;
            if (MODE == 0) {
                b0 = __ldg(&bias[n]);
                b1 = __ldg(&bias[n + 1]);
            }
            #pragma unroll
            for (int h = 0; h < 2; h++) {          // h=0: row rr, h=1: row rr+8
                int m = m0 + wm + mi * 16 + rr + h * 8;
                float v0 = acc[mi][nj][2 * h + 0];
                float v1 = acc[mi][nj][2 * h + 1];
                if (MODE == 0) {
                    v0 = fmaxf(v0 + b0, 0.f);
                    v1 = fmaxf(v1 + b1, 0.f);
                    __half h0 = __float2half(v0);
                    __half h1 = __float2half(v1);
                    __half l0 = __float2half(v0 - __half2float(h0));
                    __half l1 = __float2half(v1 - __half2float(h1));
                    uint32_t hp = pack_h2(h0, h1);
                    uint32_t lp = pack_h2(l0, l1);
                    size_t rowb = (size_t)m * K2P + n;
                    *reinterpret_cast<uint32_t*>(&outS[rowb])      = hp;
                    *reinterpret_cast<uint32_t*>(&outS[rowb + HH]) = lp;
                } else {
                    size_t zb = (size_t)blockIdx.z * BB;
                    *reinterpret_cast<float2*>(&outF[(zb + m) * NPAD2 + n]) =
                        make_float2(v0, v1);
                }
            }
        }
    }
}

// ---------------------------------------------------------------------------
// Reduce split-K partials: out[m][n] = b2[n] + sum_s part[s][m][n], n < CC
// ---------------------------------------------------------------------------
__global__ void reduce_k2_kernel(const float* __restrict__ part,
                                 const float* __restrict__ b2,
                                 float* __restrict__ out) {
    int m = blockIdx.x;
    int n = threadIdx.x;            // 160 threads
    if (n < CC) {
        float s = b2[n];
        #pragma unroll
        for (int z = 0; z < SPLITK2; z++)
            s += part[((size_t)z * BB + m) * NPAD2 + n];
        out[(size_t)m * CC + n] = s;
    }
}

// ---------------------------------------------------------------------------
// Launch. Inputs: ids i32[2048,128], emb f32[50000,512], W1 f32[512,2048],
// b1 f32[2048], W2 f32[2048,151], b2 f32[151]. Output f32[2048,151].
// ---------------------------------------------------------------------------
extern "C" void kernel_launch(void* const* d_in, const int* in_sizes, int n_in,
                              void* d_out, int out_size) {
    const int*    ids = (const int*)d_in[0];
    const float4* emb = (const float4*)d_in[1];
    const float*  W1  = (const float*)d_in[2];
    const float*  b1  = (const float*)d_in[3];
    const float*  W2  = (const float*)d_in[4];
    const float*  b2  = (const float*)d_in[5];
    float*        out = (float*)d_out;

    __half *A1, *B1, *A2, *B2;
    float* part;
    cudaGetSymbolAddress((void**)&A1, g_A1);
    cudaGetSymbolAddress((void**)&B1, g_B1);
    cudaGetSymbolAddress((void**)&A2, g_A2);
    cudaGetSymbolAddress((void**)&B2, g_B2);
    cudaGetSymbolAddress((void**)&part, g_part);

    const int SMEM_GEMM = 6 * 8192;   // 48 KB (3-stage A + B)
    static bool attr_done = false;
    if (!attr_done) {
        cudaFuncSetAttribute(hmma_gemm_kernel<0>,
                             cudaFuncAttributeMaxDynamicSharedMemorySize, SMEM_GEMM);
        cudaFuncSetAttribute(hmma_gemm_kernel<1>,
                             cudaFuncAttributeMaxDynamicSharedMemorySize, SMEM_GEMM);
        attr_done = true;
    }

    // 1) gather + masked mean -> fp16-split A1
    embed_avg_kernel<<<BB, 128>>>(ids, emb);

    // 2) weight conversions (independent of (1))
    transconv_kernel<<<dim3(HH / 32, DD / 32), dim3(32, 8)>>>(W1, B1, DD, HH, K1P);
    transconv_kernel<<<dim3(NPAD2 / 32, HH / 32), dim3(32, 8)>>>(W2, B2, HH, CC, K2P);

    // 3) h = relu(A1 . B1^T + b1) -> fp16-split A2   [2048 x 2048], K=1024
    hmma_gemm_kernel<0><<<dim3(HH / 128, BB / 128, 1), 256, SMEM_GEMM>>>(
        A1, B1, b1, A2, nullptr, K1P, K1P);

    // 4) partials = A2 . B2^T over K chunks          [2048 x 256] x 8, K=512 each
    hmma_gemm_kernel<1><<<dim3(NPAD2 / 128, BB / 128, SPLITK2), 256, SMEM_GEMM>>>(
        A2, B2, nullptr, nullptr, part, K2P, K2P / SPLITK2);

    // 5) out = b2 + sum partials (n < 151)
    reduce_k2_kernel<<<BB, 160>>>(part, b2, out);
}

// round 11
// speedup vs baseline: 1.5265x; 1.1634x over previous
#include <cuda_runtime.h>
#include <cuda_fp16.h>
#include <cstdint>

// Problem dims
#define BB 2048   // batch
#define SS 128    // seq len
#define DD 512    // embedding dim
#define HH 2048   // hidden
#define CC 151    // classes

// GEMM1: fp16 2-section split A=[hi,lo], B=[hi,hi] (a exact; drops a*b_lo)
// GEMM2: plain fp16 (h quantized once; error budget measured ~4x under bound)
#define K1P (2*DD)   // 1024
#define NPAD2 256    // padded class rows for B2
#define SPLITK2 4    // K-split for GEMM2 (2048/4 = 512 per chunk)

// Scratch (device globals — allocation is forbidden)
__device__ __half g_A1[(size_t)BB * K1P];               //  4 MB
__device__ __half g_B1[(size_t)HH * K1P];               //  4 MB
__device__ __half g_A2[(size_t)BB * HH];                //  8 MB (plain fp16 h)
__device__ __half g_B2[(size_t)NPAD2 * HH];             //  1 MB
__device__ float  g_part[(size_t)SPLITK2 * BB * NPAD2]; //  8 MB

// ---------------------------------------------------------------------------
// helpers
// ---------------------------------------------------------------------------
__device__ __forceinline__ uint32_t smem_to_u32(const void* p) {
    uint32_t a;
    asm("{ .reg .u64 t; cvta.to.shared.u64 t, %1; cvt.u32.u64 %0, t; }" : "=r"(a) : "l"(p));
    return a;
}
__device__ __forceinline__ void cp_async16(uint32_t dst, const void* src) {
    asm volatile("cp.async.cg.shared.global [%0], [%1], 16;" :: "r"(dst), "l"(src) : "memory");
}
#define CP_ASYNC_COMMIT() asm volatile("cp.async.commit_group;" ::: "memory")
#define CP_ASYNC_WAIT0()  asm volatile("cp.async.wait_group 0;" ::: "memory")
#define CP_ASYNC_WAIT1()  asm volatile("cp.async.wait_group 1;" ::: "memory")

__device__ __forceinline__ void ldm_x4(uint32_t& r0, uint32_t& r1, uint32_t& r2, uint32_t& r3,
                                       uint32_t addr) {
    asm volatile("ldmatrix.sync.aligned.m8n8.x4.shared.b16 {%0,%1,%2,%3}, [%4];"
                 : "=r"(r0), "=r"(r1), "=r"(r2), "=r"(r3) : "r"(addr));
}
__device__ __forceinline__ void mma16816(float* c, const uint32_t* a, const uint32_t* b) {
    asm volatile(
        "mma.sync.aligned.m16n8k16.row.col.f32.f16.f16.f32 "
        "{%0,%1,%2,%3}, {%4,%5,%6,%7}, {%8,%9}, {%0,%1,%2,%3};"
        : "+f"(c[0]), "+f"(c[1]), "+f"(c[2]), "+f"(c[3])
        : "r"(a[0]), "r"(a[1]), "r"(a[2]), "r"(a[3]), "r"(b[0]), "r"(b[1]));
}
__device__ __forceinline__ uint32_t pack_h2(__half lo, __half hi) {
    return ((uint32_t)__half_as_ushort(hi) << 16) | (uint32_t)__half_as_ushort(lo);
}
// smem tile: rows x 64B (BK=32 fp16). 16B chunk c in row r lives at
// r*64 + (c ^ ((r>>1)&3))*16  -> conflict-free for ldmatrix 8-row reads.
__device__ __forceinline__ uint32_t sw_off(int r, int c) {
    return (uint32_t)(r * 64 + ((c ^ ((r >> 1) & 3)) << 4));
}

// ---------------------------------------------------------------------------
// Kernel 1: embedding gather + masked mean -> fp16-split A1 [BB][K1P]
// sections: [0,DD)=hi  [DD,2DD)=lo
// Branch-free: table row 0 is all-zero, so summing it unconditionally is
// exact; the mask count comes from __syncthreads_count.
// ---------------------------------------------------------------------------
__global__ void embed_avg_kernel(const int* __restrict__ ids,
                                 const float4* __restrict__ emb) {
    int b = blockIdx.x;
    __shared__ int s_ids[SS];
    int tid = threadIdx.x;              // 0..127
    int myid = ids[b * SS + tid];
    s_ids[tid] = myid;
    int cnt = __syncthreads_count(myid != 0);   // barrier + popcount over block

    float4 acc = make_float4(0.f, 0.f, 0.f, 0.f);
    #pragma unroll 8
    for (int s = 0; s < SS; ++s) {
        float4 v = emb[s_ids[s] * (DD / 4) + tid];   // id==0 row adds zeros
        acc.x += v.x; acc.y += v.y; acc.z += v.z; acc.w += v.w;
    }
    float inv = (cnt > 0) ? (1.0f / (float)cnt) : 0.0f;
    float v[4] = {acc.x * inv, acc.y * inv, acc.z * inv, acc.w * inv};

    __half h[4], l[4];
    #pragma unroll
    for (int j = 0; j < 4; j++) {
        h[j] = __float2half(v[j]);
        l[j] = __float2half(v[j] - __half2float(h[j]));
    }
    uint2 hp = make_uint2(pack_h2(h[0], h[1]), pack_h2(h[2], h[3]));
    uint2 lp = make_uint2(pack_h2(l[0], l[1]), pack_h2(l[2], l[3]));
    size_t base = (size_t)b * K1P + tid * 4;
    *reinterpret_cast<uint2*>(&g_A1[base])      = hp;   // hi
    *reinterpret_cast<uint2*>(&g_A1[base + DD]) = lp;   // lo
}

// ---------------------------------------------------------------------------
// Transpose + convert: W [K][Nreal] f32 -> Bc [n][Kp] fp16 K-major.
// If Kp >= 2K, the hi section is duplicated at [K,2K) (GEMM1 split pairing).
// ---------------------------------------------------------------------------
__global__ void transconv_kernel(const float* __restrict__ W,
                                 __half* __restrict__ Bc,
                                 int K, int Nreal, int Kp) {
    __shared__ float sm[32][33];
    int tx = threadIdx.x, ty = threadIdx.y;   // (32, 8)
    int n0 = blockIdx.x * 32, k0 = blockIdx.y * 32;

    #pragma unroll
    for (int r = 0; r < 4; r++) {
        int kk = k0 + ty + 8 * r;
        int nn = n0 + tx;
        sm[ty + 8 * r][tx] = (nn < Nreal) ? W[(size_t)kk * Nreal + nn] : 0.f;
    }
    __syncthreads();

    #pragma unroll
    for (int r = 0; r < 4; r++) {
        int nn = n0 + ty + 8 * r;
        int kk = k0 + tx;
        __half hi = __float2half(sm[tx][ty + 8 * r]);
        size_t row = (size_t)nn * Kp;
        Bc[row + kk] = hi;
        if (Kp >= 2 * K) Bc[row + K + kk] = hi;
    }
}

// ---------------------------------------------------------------------------
// mma.sync fp16 GEMM, NT form: C[128x128] = A[128xKc] . B[128xKc]^T
// Both operands K-contiguous (row stride ld). BK=32, 3-stage cp.async
// pipeline, ONE __syncthreads per iteration.
// 8 warps: warp (wid>>2) -> 64-row half, (wid&3) -> 32-col quarter.
// MODE 0: v = relu(d + bias[n]); write plain fp16 h to outS (row stride HH).
// MODE 1: write raw f32 partial to outF[(z*BB+m)*NPAD2 + n].
// Dynamic smem: A stages 3 x 8 KB at [0,24K); B stages 3 x 8 KB at [24K,48K).
// ---------------------------------------------------------------------------
template <int MODE>
__global__ __launch_bounds__(256, 2)
void hmma_gemm_kernel(const __half* __restrict__ A,
                      const __half* __restrict__ Bm,
                      const float* __restrict__ bias,
                      __half* __restrict__ outS,
                      float* __restrict__ outF,
                      int ld, int kChunk) {
    extern __shared__ __align__(16) unsigned char smem_dyn[];
    const uint32_t sA = smem_to_u32(smem_dyn);            // 3 x 8192
    const uint32_t sB = sA + 3 * 8192;                    // 3 x 8192

    const int tid  = threadIdx.x;
    const int wid  = tid >> 5;
    const int lane = tid & 31;
    const int m0 = blockIdx.y * 128;
    const int n0 = blockIdx.x * 128;
    const int koff = blockIdx.z * kChunk;

    const __half* Ap = A + (size_t)m0 * ld + koff;
    const __half* Bp = Bm + (size_t)n0 * ld + koff;

    const int niter = kChunk / 32;

    // stage tile for iteration 'it' into stage buffer 'buf' (0..2)
    auto stage = [&](int it, int buf) {
        const __half* a_src = Ap + it * 32;
        const __half* b_src = Bp + it * 32;
        uint32_t dA = sA + buf * 8192;
        uint32_t dB = sB + buf * 8192;
        #pragma unroll
        for (int p = 0; p < 2; p++) {
            int i = p * 256 + tid;     // 0..511 : 16B chunks
            int r = i >> 2;            // row 0..127
            int c = i & 3;             // 16B chunk in row
            uint32_t off = sw_off(r, c);
            cp_async16(dA + off, a_src + (size_t)r * ld + c * 8);
            cp_async16(dB + off, b_src + (size_t)r * ld + c * 8);
        }
    };

    const int wm = (wid >> 2) * 64;
    const int wn = (wid & 3) * 32;

    float acc[4][4][4];
    #pragma unroll
    for (int i = 0; i < 4; i++)
        #pragma unroll
        for (int j = 0; j < 4; j++)
            #pragma unroll
            for (int q = 0; q < 4; q++) acc[i][j][q] = 0.f;

    // prologue: prefetch tiles 0 and 1
    stage(0, 0);
    CP_ASYNC_COMMIT();
    stage(1, 1);
    CP_ASYNC_COMMIT();

    for (int it = 0; it < niter; it++) {
        int buf = it % 3;
        CP_ASYNC_WAIT1();      // <=1 group pending -> stage(it) has landed
        __syncthreads();       // all warps past compute(it-1); buf (it-1)%3 free

        if (it + 2 < niter) {
            stage(it + 2, (it + 2) % 3);
            CP_ASYNC_COMMIT();
        }

        uint32_t aBase = sA + buf * 8192;
        uint32_t bBase = sB + buf * 8192;
        #pragma unroll
        for (int ks = 0; ks < 2; ks++) {
            uint32_t a[4][4];
            #pragma unroll
            for (int mi = 0; mi < 4; mi++) {
                int r = wm + mi * 16 + (lane & 15);
                int c = ks * 2 + (lane >> 4);
                ldm_x4(a[mi][0], a[mi][1], a[mi][2], a[mi][3], aBase + sw_off(r, c));
            }
            uint32_t b[4][2];
            #pragma unroll
            for (int nj = 0; nj < 2; nj++) {
                int r = wn + nj * 16 + (lane & 15);
                int c = ks * 2 + (lane >> 4);
                uint32_t r0, r1, r2, r3;
                ldm_x4(r0, r1, r2, r3, bBase + sw_off(r, c));
                b[nj * 2 + 0][0] = r0;  b[nj * 2 + 1][0] = r1;
                b[nj * 2 + 0][1] = r2;  b[nj * 2 + 1][1] = r3;
            }
            #pragma unroll
            for (int mi = 0; mi < 4; mi++)
                #pragma unroll
                for (int nj = 0; nj < 4; nj++)
                    mma16816(acc[mi][nj], a[mi], b[nj]);
        }
    }

    // Epilogue. acc frag (mi,nj): rows wm+mi*16 + (lane>>2) and +8;
    // cols wn+nj*8 + 2*(lane&3) + {0,1}.
    const int rr = lane >> 2;
    const int cpair = (lane & 3) * 2;
    #pragma unroll
    for (int mi = 0; mi < 4; mi++) {
        #pragma unroll
        for (int nj = 0; nj < 4; nj++) {
            int nl = wn + nj * 8 + cpair;          // local col (even)
            int n = n0 + nl;
            float b0 = 0.f, b1 = 0.f;
            if (MODE == 0) {
                b0 = __ldg(&bias[n]);
                b1 = __ldg(&bias[n + 1]);
            }
            #pragma unroll
            for (int h = 0; h < 2; h++) {          // h=0: row rr, h=1: row rr+8
                int m = m0 + wm + mi * 16 + rr + h * 8;
                float v0 = acc[mi][nj][2 * h + 0];
                float v1 = acc[mi][nj][2 * h + 1];
                if (MODE == 0) {
                    v0 = fmaxf(v0 + b0, 0.f);
                    v1 = fmaxf(v1 + b1, 0.f);
                    uint32_t hp = pack_h2(__float2half(v0), __float2half(v1));
                    *reinterpret_cast<uint32_t*>(&outS[(size_t)m * HH + n]) = hp;
                } else {
                    size_t zb = (size_t)blockIdx.z * BB;
                    *reinterpret_cast<float2*>(&outF[(zb + m) * NPAD2 + n]) =
                        make_float2(v0, v1);
                }
            }
        }
    }
}

// ---------------------------------------------------------------------------
// Reduce split-K partials: out[m][n] = b2[n] + sum_s part[s][m][n], n < CC
// ---------------------------------------------------------------------------
__global__ void reduce_k2_kernel(const float* __restrict__ part,
                                 const float* __restrict__ b2,
                                 float* __restrict__ out) {
    int m = blockIdx.x;
    int n = threadIdx.x;            // 160 threads
    if (n < CC) {
        float s = b2[n];
        #pragma unroll
        for (int z = 0; z < SPLITK2; z++)
            s += part[((size_t)z * BB + m) * NPAD2 + n];
        out[(size_t)m * CC + n] = s;
    }
}

// ---------------------------------------------------------------------------
// Launch. Inputs: ids i32[2048,128], emb f32[50000,512], W1 f32[512,2048],
// b1 f32[2048], W2 f32[2048,151], b2 f32[151]. Output f32[2048,151].
// ---------------------------------------------------------------------------
extern "C" void kernel_launch(void* const* d_in, const int* in_sizes, int n_in,
                              void* d_out, int out_size) {
    const int*    ids = (const int*)d_in[0];
    const float4* emb = (const float4*)d_in[1];
    const float*  W1  = (const float*)d_in[2];
    const float*  b1  = (const float*)d_in[3];
    const float*  W2  = (const float*)d_in[4];
    const float*  b2  = (const float*)d_in[5];
    float*        out = (float*)d_out;

    __half *A1, *B1, *A2, *B2;
    float* part;
    cudaGetSymbolAddress((void**)&A1, g_A1);
    cudaGetSymbolAddress((void**)&B1, g_B1);
    cudaGetSymbolAddress((void**)&A2, g_A2);
    cudaGetSymbolAddress((void**)&B2, g_B2);
    cudaGetSymbolAddress((void**)&part, g_part);

    const int SMEM_GEMM = 6 * 8192;   // 48 KB (3-stage A + B)
    static bool attr_done = false;
    if (!attr_done) {
        cudaFuncSetAttribute(hmma_gemm_kernel<0>,
                             cudaFuncAttributeMaxDynamicSharedMemorySize, SMEM_GEMM);
        cudaFuncSetAttribute(hmma_gemm_kernel<1>,
                             cudaFuncAttributeMaxDynamicSharedMemorySize, SMEM_GEMM);
        attr_done = true;
    }

    // 1) gather + masked mean -> fp16-split A1
    embed_avg_kernel<<<BB, 128>>>(ids, emb);

    // 2) weight conversions (independent of (1))
    transconv_kernel<<<dim3(HH / 32, DD / 32), dim3(32, 8)>>>(W1, B1, DD, HH, K1P);
    transconv_kernel<<<dim3(NPAD2 / 32, HH / 32), dim3(32, 8)>>>(W2, B2, HH, CC, HH);

    // 3) h = relu(A1 . B1^T + b1) -> plain fp16 A2   [2048 x 2048], K=1024
    hmma_gemm_kernel<0><<<dim3(HH / 128, BB / 128, 1), 256, SMEM_GEMM>>>(
        A1, B1, b1, A2, nullptr, K1P, K1P);

    // 4) partials = A2 . B2^T over K chunks          [2048 x 256] x 4, K=512 each
    hmma_gemm_kernel<1><<<dim3(NPAD2 / 128, BB / 128, SPLITK2), 256, SMEM_GEMM>>>(
        A2, B2, nullptr, nullptr, part, HH, HH / SPLITK2);

    // 5) out = b2 + sum partials (n < 151)
    reduce_k2_kernel<<<BB, 160>>>(part, b2, out);
}

// round 12
// speedup vs baseline: 1.8717x; 1.2261x over previous
#include <cuda_runtime.h>
#include <cuda_fp16.h>
#include <cstdint>

// Problem dims
#define BB 2048   // batch
#define SS 128    // seq len
#define DD 512    // embedding dim
#define HH 2048   // hidden
#define CC 151    // classes

// All-fp16 pipeline. Error terms (each ~1.3e-4 rms, compose in quadrature):
//   W1, W2 fp16 quantization; avg fp16 quantization; h fp16 quantization.
// Measured trail: 1.37e-4 (W only) -> 1.86e-4 (+h) -> predicted ~2.3e-4 (+avg).
#define NPAD2 256    // padded class rows for B2
#define SPLITK2 4    // K-split for GEMM2 (2048/4 = 512 per chunk)

// Scratch (device globals — allocation is forbidden)
__device__ __half g_A1[(size_t)BB * DD];                //  2 MB (plain fp16 avg)
__device__ __half g_B1[(size_t)HH * DD];                //  2 MB
__device__ __half g_A2[(size_t)BB * HH];                //  8 MB (plain fp16 h)
__device__ __half g_B2[(size_t)NPAD2 * HH];             //  1 MB
__device__ float  g_part[(size_t)SPLITK2 * BB * NPAD2]; //  8 MB

// ---------------------------------------------------------------------------
// helpers
// ---------------------------------------------------------------------------
__device__ __forceinline__ uint32_t smem_to_u32(const void* p) {
    uint32_t a;
    asm("{ .reg .u64 t; cvta.to.shared.u64 t, %1; cvt.u32.u64 %0, t; }" : "=r"(a) : "l"(p));
    return a;
}
__device__ __forceinline__ void cp_async16(uint32_t dst, const void* src) {
    asm volatile("cp.async.cg.shared.global [%0], [%1], 16;" :: "r"(dst), "l"(src) : "memory");
}
#define CP_ASYNC_COMMIT() asm volatile("cp.async.commit_group;" ::: "memory")
#define CP_ASYNC_WAIT0()  asm volatile("cp.async.wait_group 0;" ::: "memory")
#define CP_ASYNC_WAIT1()  asm volatile("cp.async.wait_group 1;" ::: "memory")

__device__ __forceinline__ void ldm_x4(uint32_t& r0, uint32_t& r1, uint32_t& r2, uint32_t& r3,
                                       uint32_t addr) {
    asm volatile("ldmatrix.sync.aligned.m8n8.x4.shared.b16 {%0,%1,%2,%3}, [%4];"
                 : "=r"(r0), "=r"(r1), "=r"(r2), "=r"(r3) : "r"(addr));
}
__device__ __forceinline__ void mma16816(float* c, const uint32_t* a, const uint32_t* b) {
    asm volatile(
        "mma.sync.aligned.m16n8k16.row.col.f32.f16.f16.f32 "
        "{%0,%1,%2,%3}, {%4,%5,%6,%7}, {%8,%9}, {%0,%1,%2,%3};"
        : "+f"(c[0]), "+f"(c[1]), "+f"(c[2]), "+f"(c[3])
        : "r"(a[0]), "r"(a[1]), "r"(a[2]), "r"(a[3]), "r"(b[0]), "r"(b[1]));
}
__device__ __forceinline__ uint32_t pack_h2(__half lo, __half hi) {
    return ((uint32_t)__half_as_ushort(hi) << 16) | (uint32_t)__half_as_ushort(lo);
}
// smem tile: rows x 64B (BK=32 fp16). 16B chunk c in row r lives at
// r*64 + (c ^ ((r>>1)&3))*16  -> conflict-free for ldmatrix 8-row reads.
__device__ __forceinline__ uint32_t sw_off(int r, int c) {
    return (uint32_t)(r * 64 + ((c ^ ((r >> 1) & 3)) << 4));
}

// ---------------------------------------------------------------------------
// Kernel 1: embedding gather + masked mean -> plain fp16 avg [BB][DD]
// Branch-free: table row 0 is all-zero, so summing it unconditionally is
// exact; the mask count comes from __syncthreads_count.
// ---------------------------------------------------------------------------
__global__ void embed_avg_kernel(const int* __restrict__ ids,
                                 const float4* __restrict__ emb) {
    int b = blockIdx.x;
    __shared__ int s_ids[SS];
    int tid = threadIdx.x;              // 0..127
    int myid = ids[b * SS + tid];
    s_ids[tid] = myid;
    int cnt = __syncthreads_count(myid != 0);   // barrier + popcount over block

    float4 acc = make_float4(0.f, 0.f, 0.f, 0.f);
    #pragma unroll 8
    for (int s = 0; s < SS; ++s) {
        float4 v = emb[s_ids[s] * (DD / 4) + tid];   // id==0 row adds zeros
        acc.x += v.x; acc.y += v.y; acc.z += v.z; acc.w += v.w;
    }
    float inv = (cnt > 0) ? (1.0f / (float)cnt) : 0.0f;
    uint2 hp = make_uint2(
        pack_h2(__float2half(acc.x * inv), __float2half(acc.y * inv)),
        pack_h2(__float2half(acc.z * inv), __float2half(acc.w * inv)));
    *reinterpret_cast<uint2*>(&g_A1[(size_t)b * DD + tid * 4]) = hp;
}

// ---------------------------------------------------------------------------
// Transpose + convert: W [K][Nreal] f32 -> Bc [n][K] fp16 K-major.
// ---------------------------------------------------------------------------
__global__ void transconv_kernel(const float* __restrict__ W,
                                 __half* __restrict__ Bc,
                                 int K, int Nreal) {
    __shared__ float sm[32][33];
    int tx = threadIdx.x, ty = threadIdx.y;   // (32, 8)
    int n0 = blockIdx.x * 32, k0 = blockIdx.y * 32;

    #pragma unroll
    for (int r = 0; r < 4; r++) {
        int kk = k0 + ty + 8 * r;
        int nn = n0 + tx;
        sm[ty + 8 * r][tx] = (nn < Nreal) ? W[(size_t)kk * Nreal + nn] : 0.f;
    }
    __syncthreads();

    #pragma unroll
    for (int r = 0; r < 4; r++) {
        int nn = n0 + ty + 8 * r;
        int kk = k0 + tx;
        Bc[(size_t)nn * K + kk] = __float2half(sm[tx][ty + 8 * r]);
    }
}

// ---------------------------------------------------------------------------
// mma.sync fp16 GEMM, NT form: C[128x128] = A[128xKc] . B[128xKc]^T
// Both operands K-contiguous (row stride ld). BK=32, 3-stage cp.async
// pipeline, ONE __syncthreads per iteration.
// 8 warps: warp (wid>>2) -> 64-row half, (wid&3) -> 32-col quarter.
// MODE 0: v = relu(d + bias[n]); write plain fp16 h to outS (row stride HH).
// MODE 1: write raw f32 partial to outF[(z*BB+m)*NPAD2 + n].
// Dynamic smem: A stages 3 x 8 KB at [0,24K); B stages 3 x 8 KB at [24K,48K).
// ---------------------------------------------------------------------------
template <int MODE>
__global__ __launch_bounds__(256, 2)
void hmma_gemm_kernel(const __half* __restrict__ A,
                      const __half* __restrict__ Bm,
                      const float* __restrict__ bias,
                      __half* __restrict__ outS,
                      float* __restrict__ outF,
                      int ld, int kChunk) {
    extern __shared__ __align__(16) unsigned char smem_dyn[];
    const uint32_t sA = smem_to_u32(smem_dyn);            // 3 x 8192
    const uint32_t sB = sA + 3 * 8192;                    // 3 x 8192

    const int tid  = threadIdx.x;
    const int wid  = tid >> 5;
    const int lane = tid & 31;
    const int m0 = blockIdx.y * 128;
    const int n0 = blockIdx.x * 128;
    const int koff = blockIdx.z * kChunk;

    const __half* Ap = A + (size_t)m0 * ld + koff;
    const __half* Bp = Bm + (size_t)n0 * ld + koff;

    const int niter = kChunk / 32;

    // stage tile for iteration 'it' into stage buffer 'buf' (0..2)
    auto stage = [&](int it, int buf) {
        const __half* a_src = Ap + it * 32;
        const __half* b_src = Bp + it * 32;
        uint32_t dA = sA + buf * 8192;
        uint32_t dB = sB + buf * 8192;
        #pragma unroll
        for (int p = 0; p < 2; p++) {
            int i = p * 256 + tid;     // 0..511 : 16B chunks
            int r = i >> 2;            // row 0..127
            int c = i & 3;             // 16B chunk in row
            uint32_t off = sw_off(r, c);
            cp_async16(dA + off, a_src + (size_t)r * ld + c * 8);
            cp_async16(dB + off, b_src + (size_t)r * ld + c * 8);
        }
    };

    const int wm = (wid >> 2) * 64;
    const int wn = (wid & 3) * 32;

    float acc[4][4][4];
    #pragma unroll
    for (int i = 0; i < 4; i++)
        #pragma unroll
        for (int j = 0; j < 4; j++)
            #pragma unroll
            for (int q = 0; q < 4; q++) acc[i][j][q] = 0.f;

    // prologue: prefetch tiles 0 and 1
    stage(0, 0);
    CP_ASYNC_COMMIT();
    stage(1, 1);
    CP_ASYNC_COMMIT();

    for (int it = 0; it < niter; it++) {
        int buf = it % 3;
        CP_ASYNC_WAIT1();      // <=1 group pending -> stage(it) has landed
        __syncthreads();       // all warps past compute(it-1); buf (it-1)%3 free

        if (it + 2 < niter) {
            stage(it + 2, (it + 2) % 3);
            CP_ASYNC_COMMIT();
        }

        uint32_t aBase = sA + buf * 8192;
        uint32_t bBase = sB + buf * 8192;
        #pragma unroll
        for (int ks = 0; ks < 2; ks++) {
            uint32_t a[4][4];
            #pragma unroll
            for (int mi = 0; mi < 4; mi++) {
                int r = wm + mi * 16 + (lane & 15);
                int c = ks * 2 + (lane >> 4);
                ldm_x4(a[mi][0], a[mi][1], a[mi][2], a[mi][3], aBase + sw_off(r, c));
            }
            uint32_t b[4][2];
            #pragma unroll
            for (int nj = 0; nj < 2; nj++) {
                int r = wn + nj * 16 + (lane & 15);
                int c = ks * 2 + (lane >> 4);
                uint32_t r0, r1, r2, r3;
                ldm_x4(r0, r1, r2, r3, bBase + sw_off(r, c));
                b[nj * 2 + 0][0] = r0;  b[nj * 2 + 1][0] = r1;
                b[nj * 2 + 0][1] = r2;  b[nj * 2 + 1][1] = r3;
            }
            #pragma unroll
            for (int mi = 0; mi < 4; mi++)
                #pragma unroll
                for (int nj = 0; nj < 4; nj++)
                    mma16816(acc[mi][nj], a[mi], b[nj]);
        }
    }

    // Epilogue. acc frag (mi,nj): rows wm+mi*16 + (lane>>2) and +8;
    // cols wn+nj*8 + 2*(lane&3) + {0,1}.
    const int rr = lane >> 2;
    const int cpair = (lane & 3) * 2;
    #pragma unroll
    for (int mi = 0; mi < 4; mi++) {
        #pragma unroll
        for (int nj = 0; nj < 4; nj++) {
            int nl = wn + nj * 8 + cpair;          // local col (even)
            int n = n0 + nl;
            float b0 = 0.f, b1 = 0.f;
            if (MODE == 0) {
                b0 = __ldg(&bias[n]);
                b1 = __ldg(&bias[n + 1]);
            }
            #pragma unroll
            for (int h = 0; h < 2; h++) {          // h=0: row rr, h=1: row rr+8
                int m = m0 + wm + mi * 16 + rr + h * 8;
                float v0 = acc[mi][nj][2 * h + 0];
                float v1 = acc[mi][nj][2 * h + 1];
                if (MODE == 0) {
                    v0 = fmaxf(v0 + b0, 0.f);
                    v1 = fmaxf(v1 + b1, 0.f);
                    uint32_t hp = pack_h2(__float2half(v0), __float2half(v1));
                    *reinterpret_cast<uint32_t*>(&outS[(size_t)m * HH + n]) = hp;
                } else {
                    size_t zb = (size_t)blockIdx.z * BB;
                    *reinterpret_cast<float2*>(&outF[(zb + m) * NPAD2 + n]) =
                        make_float2(v0, v1);
                }
            }
        }
    }
}

// ---------------------------------------------------------------------------
// Reduce split-K partials: out[m][n] = b2[n] + sum_s part[s][m][n], n < CC
// ---------------------------------------------------------------------------
__global__ void reduce_k2_kernel(const float* __restrict__ part,
                                 const float* __restrict__ b2,
                                 float* __restrict__ out) {
    int m = blockIdx.x;
    int n = threadIdx.x;            // 160 threads
    if (n < CC) {
        float s = b2[n];
        #pragma unroll
        for (int z = 0; z < SPLITK2; z++)
            s += part[((size_t)z * BB + m) * NPAD2 + n];
        out[(size_t)m * CC + n] = s;
    }
}

// ---------------------------------------------------------------------------
// Launch. Inputs: ids i32[2048,128], emb f32[50000,512], W1 f32[512,2048],
// b1 f32[2048], W2 f32[2048,151], b2 f32[151]. Output f32[2048,151].
// ---------------------------------------------------------------------------
extern "C" void kernel_launch(void* const* d_in, const int* in_sizes, int n_in,
                              void* d_out, int out_size) {
    const int*    ids = (const int*)d_in[0];
    const float4* emb = (const float4*)d_in[1];
    const float*  W1  = (const float*)d_in[2];
    const float*  b1  = (const float*)d_in[3];
    const float*  W2  = (const float*)d_in[4];
    const float*  b2  = (const float*)d_in[5];
    float*        out = (float*)d_out;

    __half *A1, *B1, *A2, *B2;
    float* part;
    cudaGetSymbolAddress((void**)&A1, g_A1);
    cudaGetSymbolAddress((void**)&B1, g_B1);
    cudaGetSymbolAddress((void**)&A2, g_A2);
    cudaGetSymbolAddress((void**)&B2, g_B2);
    cudaGetSymbolAddress((void**)&part, g_part);

    const int SMEM_GEMM = 6 * 8192;   // 48 KB (3-stage A + B)
    static bool attr_done = false;
    if (!attr_done) {
        cudaFuncSetAttribute(hmma_gemm_kernel<0>,
                             cudaFuncAttributeMaxDynamicSharedMemorySize, SMEM_GEMM);
        cudaFuncSetAttribute(hmma_gemm_kernel<1>,
                             cudaFuncAttributeMaxDynamicSharedMemorySize, SMEM_GEMM);
        attr_done = true;
    }

    // 1) gather + masked mean -> plain fp16 avg
    embed_avg_kernel<<<BB, 128>>>(ids, emb);

    // 2) weight conversions (independent of (1))
    transconv_kernel<<<dim3(HH / 32, DD / 32), dim3(32, 8)>>>(W1, B1, DD, HH);
    transconv_kernel<<<dim3(NPAD2 / 32, HH / 32), dim3(32, 8)>>>(W2, B2, HH, CC);

    // 3) h = relu(A1 . B1^T + b1) -> plain fp16 A2   [2048 x 2048], K=512
    hmma_gemm_kernel<0><<<dim3(HH / 128, BB / 128, 1), 256, SMEM_GEMM>>>(
        A1, B1, b1, A2, nullptr, DD, DD);

    // 4) partials = A2 . B2^T over K chunks          [2048 x 256] x 4, K=512 each
    hmma_gemm_kernel<1><<<dim3(NPAD2 / 128, BB / 128, SPLITK2), 256, SMEM_GEMM>>>(
        A2, B2, nullptr, nullptr, part, HH, HH / SPLITK2);

    // 5) out = b2 + sum partials (n < 151)
    reduce_k2_kernel<<<BB, 160>>>(part, b2, out);
}